// round 8
// baseline (speedup 1.0000x reference)
#include <cuda_runtime.h>

using ull = unsigned long long;

namespace {
constexpr int CH = 16;
constexpr int H = 192, W = 192;
constexpr unsigned FULL = 0xffffffffu;
constexpr int NT = 256;

// main tile: 28 rows x 24 cols output; corr 30 rows; noise rows 34 (R..R+4), cols 36
constexpr int NH = 34, NW = 36;
constexpr int CRH = 30;
constexpr int HSR = 24;                      // h cols = out cols (centers 1..24)
constexpr int SN_FLOATS  = CH * NH * NW;     // 19584
constexpr int SHS_FLOATS = 9 * CRH * HSR;    // 6480
constexpr int SMEM_BYTES = (SN_FLOATS + SHS_FLOATS) * 4;  // 104256

// top strip: rows 0..3, x-tiles of 96
constexpr int T_NH = 10, T_NW = 108, T_HSR = 96, T_CR = 6;
constexpr int T_SN = CH * T_NH * T_NW;       // 17280
// side strips: one 24-row band, left+right 4-col strips
constexpr int S_NH = 30, S_NW = 16, S_HSR = 4, S_CR = 26;
constexpr int S_SN = CH * S_NH * S_NW;       // 7680 per side
constexpr int S_HS = 9 * S_CR * S_HSR;       // 936 per side

constexpr int N_MAIN = 448;
constexpr int N_TOP  = 16;
constexpr int N_SIDE = 64;
constexpr int NBLOCKS = N_MAIN + N_TOP + N_SIDE;  // 528
}

__device__ __forceinline__ ull pk(float lo, float hi) {
    ull r; asm("mov.b64 %0, {%1,%2};" : "=l"(r) : "f"(lo), "f"(hi)); return r;
}
__device__ __forceinline__ void upk(ull v, float& lo, float& hi) {
    asm("mov.b64 {%0,%1}, %2;" : "=f"(lo), "=f"(hi) : "l"(v));
}
__device__ __forceinline__ void ffma2(ull& acc, ull m, ull s) {
    asm("fma.rn.f32x2 %0, %1, %2, %0;" : "+l"(acc) : "l"(m), "l"(s));
}

// corr (16ch, 4 cols, 9 dj) + horizontal 3-sum.
// h[dj][j] = 3-sum centered at local corr col q0+1+j (needs own c0..c3 + right c0,c1).
// cen pre-scaled by 1/144. Odd dj packs the ACC (c1,c2) so all f32x2 operands are
// free even-aligned register pairs; edges are scalar FFMAs (no operand MOV packs).
__device__ __forceinline__ void corr_hsum(const float* __restrict__ base, int chStride,
                                          const ull* __restrict__ cE0,
                                          const ull* __restrict__ cE1,
                                          float (&h)[9][4])
{
    ull aE0[5], aE1[5], aM[4];
    float a0s[4], a3s[4];
    #pragma unroll
    for (int i = 0; i < 5; i++) { aE0[i] = 0ull; aE1[i] = 0ull; }
    #pragma unroll
    for (int i = 0; i < 4; i++) { aM[i] = 0ull; a0s[i] = 0.0f; a3s[i] = 0.0f; }

    #pragma unroll
    for (int c = 0; c < CH; c++) {
        const float* row = base + c * chStride;
        float4 A = *(const float4*)(row);
        float4 B = *(const float4*)(row + 4);
        float4 C = *(const float4*)(row + 8);
        ull E0 = pk(A.x, A.y), E1 = pk(A.z, A.w);
        ull E2 = pk(B.x, B.y), E3 = pk(B.z, B.w);
        ull E4 = pk(C.x, C.y), E5 = pk(C.z, C.w);
        ull m0 = cE0[c], m1 = cE1[c];
        float c0, c1, c2, c3;
        upk(m0, c0, c1); upk(m1, c2, c3);
        ull mM = pk(c1, c2);
        // even dj
        ffma2(aE0[0], m0, E0); ffma2(aE1[0], m1, E1);   // dj=0
        ffma2(aE0[1], m0, E1); ffma2(aE1[1], m1, E2);   // dj=2
        ffma2(aE0[2], m0, E2); ffma2(aE1[2], m1, E3);   // dj=4
        ffma2(aE0[3], m0, E3); ffma2(aE1[3], m1, E4);   // dj=6
        ffma2(aE0[4], m0, E4); ffma2(aE1[4], m1, E5);   // dj=8
        // odd dj middle pairs (cols 1,2)
        ffma2(aM[0], mM, E1); ffma2(aM[1], mM, E2);
        ffma2(aM[2], mM, E3); ffma2(aM[3], mM, E4);
        // odd dj edges (cols 0,3), scalar
        a0s[0] = fmaf(c0, A.y, a0s[0]);  a3s[0] = fmaf(c3, B.x, a3s[0]);  // dj=1
        a0s[1] = fmaf(c0, A.w, a0s[1]);  a3s[1] = fmaf(c3, B.z, a3s[1]);  // dj=3
        a0s[2] = fmaf(c0, B.y, a0s[2]);  a3s[2] = fmaf(c3, C.x, a3s[2]);  // dj=5
        a0s[3] = fmaf(c0, B.w, a0s[3]);  a3s[3] = fmaf(c3, C.z, a3s[3]);  // dj=7
    }

    #pragma unroll
    for (int dj = 0; dj < 9; dj++) {
        float c0, c1, c2, c3;
        if ((dj & 1) == 0) {
            upk(aE0[dj >> 1], c0, c1); upk(aE1[dj >> 1], c2, c3);
        } else {
            c0 = a0s[dj >> 1]; upk(aM[dj >> 1], c1, c2); c3 = a3s[dj >> 1];
        }
        float c4 = __shfl_down_sync(FULL, c0, 1);
        float c5 = __shfl_down_sync(FULL, c1, 1);
        float t12 = c1 + c2, t34 = c3 + c4;
        h[dj][0] = c0 + t12;
        h[dj][1] = t12 + c3;
        h[dj][2] = c2 + t34;
        h[dj][3] = t34 + c5;
    }
}

__global__ __launch_bounds__(NT, 2)
void noisecorr_kernel(const float* __restrict__ noise, float* __restrict__ out)
{
    extern __shared__ float smem[];
    const int t   = threadIdx.x;
    const int bid = blockIdx.x;
    const float inv = 1.0f / 144.0f;

    if (bid < N_MAIN) {
        // ================= MAIN: di 4..8 direct + mirror scatter =================
        float* sN  = smem;                  // [16][34][36], row 0 = global y0-1
        float* sHS = smem + SN_FLOATS;      // [9][30][24]
        const int b   = bid / 56;
        const int rem = bid - b * 56;
        const int ty  = rem >> 3;
        const int tx  = rem & 7;
        const int y0  = (ty < 6) ? ty * 28 : 164;   // band 6 overlaps band 5 (benign)
        const int tx0 = tx * 24;
        const float* nb = noise + (size_t)b * CH * H * W;

        for (int idx = t; idx < SN_FLOATS; idx += NT) {
            int c   = idx / (NH * NW);
            int r2  = idx - c * (NH * NW);
            int nr  = r2 / NW;
            int nc  = r2 - nr * NW;
            int gy = y0 - 1 + nr, gx = tx0 - 5 + nc;
            float v = 0.0f;
            if ((unsigned)gy < (unsigned)H && (unsigned)gx < (unsigned)W)
                v = nb[(c * H + gy) * W + gx];
            sN[idx] = v;
        }
        __syncthreads();

        const int r  = t >> 3;               // 0..31; rows 30,31 clamped
        const int g  = t & 7;
        const int q0 = g * 4;
        const int qc = min(q0, 24);
        const int qv = min(q0, 20);
        const int rc = min(r, 29);
        const bool hstore = (r < 30) && (g < 6);
        const bool vstore = (r >= 1) && (r <= 28) && (g <= 5);
        const int  rv = min(max(r, 1), 28);
        const bool xs = (tx >= 1) && (tx <= 6);
        const bool ys = (ty != 6);

        ull cE0[CH], cE1[CH];
        #pragma unroll
        for (int c = 0; c < CH; c++) {
            float4 v = *(const float4*)&sN[(c * NH + rc) * NW + qc + 4];
            cE0[c] = pk(v.x * inv, v.y * inv);
            cE1[c] = pk(v.z * inv, v.w * inv);
        }

        #pragma unroll 1
        for (int k = 0; k < 5; k++) {        // di = k + 4
            float h[9][4];
            corr_hsum(&sN[(rc + k) * NW + qc], NH * NW, cE0, cE1, h);

            __syncthreads();
            if (hstore) {
                #pragma unroll
                for (int dj = 0; dj < 9; dj++)
                    *(float4*)&sHS[(dj * CRH + r) * HSR + q0] =
                        make_float4(h[dj][0], h[dj][1], h[dj][2], h[dj][3]);
            }
            __syncthreads();

            const int oy = y0 + r - 1;
            #pragma unroll
            for (int dj = 0; dj < 9; dj++) {
                float4 hm = *(const float4*)&sHS[(dj * CRH + rv - 1) * HSR + qv];
                float4 hp = *(const float4*)&sHS[(dj * CRH + rv + 1) * HSR + qv];
                if (vstore) {
                    float4 o;
                    o.x = hm.x + h[dj][0] + hp.x;
                    o.y = hm.y + h[dj][1] + hp.y;
                    o.z = hm.z + h[dj][2] + hp.z;
                    o.w = hm.w + h[dj][3] + hp.w;
                    const int p = (k + 4) * 9 + dj;
                    float* ob = out + (((size_t)b * 81 + p) * H + oy) * W + tx0 + q0;
                    *(float4*)ob = o;

                    if (k >= 1) {   // mirror: out_{80-p}(y+k, x+dj-4), bitwise equal
                        const int ym = oy + k;
                        if (ys || ym < H) {
                            const int pm = 80 - p;
                            const int xb = tx0 + q0 + (dj - 4);
                            float* om = out + (((size_t)b * 81 + pm) * H + ym) * W;
                            if (xs) {
                                if ((dj & 1) == 0) {
                                    *(float2*)&om[xb]     = make_float2(o.x, o.y);
                                    *(float2*)&om[xb + 2] = make_float2(o.z, o.w);
                                } else {
                                    om[xb] = o.x;
                                    *(float2*)&om[xb + 1] = make_float2(o.y, o.z);
                                    om[xb + 3] = o.w;
                                }
                            } else {
                                if ((unsigned)(xb + 0) < (unsigned)W) om[xb + 0] = o.x;
                                if ((unsigned)(xb + 1) < (unsigned)W) om[xb + 1] = o.y;
                                if ((unsigned)(xb + 2) < (unsigned)W) om[xb + 2] = o.z;
                                if ((unsigned)(xb + 3) < (unsigned)W) om[xb + 3] = o.w;
                            }
                        }
                    }
                }
            }
        }
    } else if (bid < N_MAIN + N_TOP) {
        // ================= TOP STRIP: planes di 0..3, rows 0..3, full width ======
        float* sN  = smem;
        float* sHS = smem + T_SN;
        const int idx0 = bid - N_MAIN;
        const int b    = idx0 >> 1;
        const int tx0  = (idx0 & 1) * 96;
        const float* nb = noise + (size_t)b * CH * H * W;

        for (int idx = t; idx < T_SN; idx += NT) {
            int c   = idx / (T_NH * T_NW);
            int r2  = idx - c * (T_NH * T_NW);
            int nr  = r2 / T_NW;
            int nc  = r2 - nr * T_NW;
            int gy = nr - 5, gx = tx0 - 5 + nc;
            float v = 0.0f;
            if ((unsigned)gy < (unsigned)H && (unsigned)gx < (unsigned)W)
                v = nb[(c * H + gy) * W + gx];
            sN[idx] = v;
        }
        __syncthreads();

        const int r  = t >> 5;          // 0..7; rows 6,7 clamped
        const int g  = t & 31;
        const int q0 = g * 4;
        const int qc = min(q0, 96);
        const int qv = min(q0, 92);
        const int rc = min(r, 5);
        const bool hstore = (r < 6) && (g < 24);
        const bool vstore = (r >= 1) && (r <= 4) && (g <= 23);
        const int  rv = min(max(r, 1), 4);

        ull cE0[CH], cE1[CH];
        #pragma unroll
        for (int c = 0; c < CH; c++) {
            float4 v = *(const float4*)&sN[(c * T_NH + rc + 4) * T_NW + qc + 4];
            cE0[c] = pk(v.x * inv, v.y * inv);
            cE1[c] = pk(v.z * inv, v.w * inv);
        }

        #pragma unroll 1
        for (int di = 0; di < 4; di++) {
            float h[9][4];
            corr_hsum(&sN[(rc + di) * T_NW + qc], T_NH * T_NW, cE0, cE1, h);

            __syncthreads();
            if (hstore) {
                #pragma unroll
                for (int dj = 0; dj < 9; dj++)
                    *(float4*)&sHS[(dj * T_CR + r) * T_HSR + q0] =
                        make_float4(h[dj][0], h[dj][1], h[dj][2], h[dj][3]);
            }
            __syncthreads();

            const int oy = r - 1;
            #pragma unroll
            for (int dj = 0; dj < 9; dj++) {
                float4 hm = *(const float4*)&sHS[(dj * T_CR + rv - 1) * T_HSR + qv];
                float4 hp = *(const float4*)&sHS[(dj * T_CR + rv + 1) * T_HSR + qv];
                if (vstore) {
                    float4 o;
                    o.x = hm.x + h[dj][0] + hp.x;
                    o.y = hm.y + h[dj][1] + hp.y;
                    o.z = hm.z + h[dj][2] + hp.z;
                    o.w = hm.w + h[dj][3] + hp.w;
                    const int p = di * 9 + dj;
                    float* ob = out + (((size_t)b * 81 + p) * H + oy) * W + tx0 + q0;
                    *(float4*)ob = o;
                }
            }
        }
    } else {
        // ================= SIDE STRIPS: planes di 0..3, cols 0..3 & 188..191 =====
        float* sNL  = smem;
        float* sNR  = smem + S_SN;
        float* sHSL = smem + 2 * S_SN;
        float* sHSR = smem + 2 * S_SN + S_HS;
        const int idx0 = bid - N_MAIN - N_TOP;
        const int b = idx0 >> 3;
        const int k = idx0 & 7;
        const int y0 = (k == 7) ? 168 : 4 + 24 * k;
        const float* nb = noise + (size_t)b * CH * H * W;

        for (int idx = t; idx < 2 * S_SN; idx += NT) {
            int side = idx / S_SN;
            int w    = idx - side * S_SN;
            int c    = w / (S_NH * S_NW);
            int r2   = w - c * (S_NH * S_NW);
            int nr   = r2 >> 4;
            int nc   = r2 & 15;
            int gy = y0 - 5 + nr;
            int gx = (side ? 183 : -5) + nc;
            float v = 0.0f;
            if ((unsigned)gy < (unsigned)H && (unsigned)gx < (unsigned)W)
                v = nb[(c * H + gy) * W + gx];
            smem[side ? (S_SN + w) : w] = v;
        }
        __syncthreads();

        const bool active = (t < 128);
        const int r  = t >> 2;
        const int g  = t & 3;
        const int gg = g & 1;
        const int sd = g >> 1;
        const int q0 = gg * 4;
        const int rc = min(r, 25);
        const bool hstore = active && (gg == 0) && (r < 26);
        const bool vstore = active && (gg == 0) && (r >= 1) && (r <= 24);
        const int  rv = min(max(r, 1), 24);
        float* sNs  = sd ? sNR : sNL;
        float* sHSs = sd ? sHSR : sHSL;
        const int ox = sd ? 188 : 0;

        ull cE0[CH], cE1[CH];
        if (active) {
            #pragma unroll
            for (int c = 0; c < CH; c++) {
                float4 v = *(const float4*)&sNs[(c * S_NH + rc + 4) * S_NW + q0 + 4];
                cE0[c] = pk(v.x * inv, v.y * inv);
                cE1[c] = pk(v.z * inv, v.w * inv);
            }
        }

        #pragma unroll 1
        for (int di = 0; di < 4; di++) {
            float h[9][4];
            if (active)
                corr_hsum(&sNs[(rc + di) * S_NW + q0], S_NH * S_NW, cE0, cE1, h);

            __syncthreads();
            if (hstore) {
                #pragma unroll
                for (int dj = 0; dj < 9; dj++)
                    *(float4*)&sHSs[(dj * S_CR + r) * S_HSR] =
                        make_float4(h[dj][0], h[dj][1], h[dj][2], h[dj][3]);
            }
            __syncthreads();

            if (active) {
                const int oy = y0 + r - 1;
                #pragma unroll
                for (int dj = 0; dj < 9; dj++) {
                    float4 hm = *(const float4*)&sHSs[(dj * S_CR + rv - 1) * S_HSR];
                    float4 hp = *(const float4*)&sHSs[(dj * S_CR + rv + 1) * S_HSR];
                    if (vstore) {
                        float4 o;
                        o.x = hm.x + h[dj][0] + hp.x;
                        o.y = hm.y + h[dj][1] + hp.y;
                        o.z = hm.z + h[dj][2] + hp.z;
                        o.w = hm.w + h[dj][3] + hp.w;
                        const int p = di * 9 + dj;
                        float* ob = out + (((size_t)b * 81 + p) * H + oy) * W + ox;
                        *(float4*)ob = o;
                    }
                }
            }
        }
    }
}

extern "C" void kernel_launch(void* const* d_in, const int* in_sizes, int n_in,
                              void* d_out, int out_size)
{
    const float* noise = (const float*)d_in[0];
    float* out = (float*)d_out;
    (void)in_sizes; (void)n_in; (void)out_size;

    cudaFuncSetAttribute(noisecorr_kernel,
                         cudaFuncAttributeMaxDynamicSharedMemorySize, SMEM_BYTES);

    noisecorr_kernel<<<NBLOCKS, NT, SMEM_BYTES>>>(noise, out);
}